// round 3
// baseline (speedup 1.0000x reference)
#include <cuda_runtime.h>
#include <cstdint>

#define T_STEPS 64

// ---------------- threefry2x32 (exact JAX) ----------------
__device__ __forceinline__ uint32_t rotl32(uint32_t x, int d){ return __funnelshift_l(x, x, d); }

__device__ __forceinline__ void threefry(uint32_t k0, uint32_t k1, uint32_t x0, uint32_t x1,
                                         uint32_t& o0, uint32_t& o1){
  uint32_t k2 = k0 ^ k1 ^ 0x1BD11BDAu;
  x0 += k0; x1 += k1;
  #define TFR(a,b,c,d) \
    x0 += x1; x1 = rotl32(x1,a); x1 ^= x0; \
    x0 += x1; x1 = rotl32(x1,b); x1 ^= x0; \
    x0 += x1; x1 = rotl32(x1,c); x1 ^= x0; \
    x0 += x1; x1 = rotl32(x1,d); x1 ^= x0;
  TFR(13,15,26,6)  x0 += k1; x1 += k2 + 1u;
  TFR(17,29,16,24) x0 += k2; x1 += k0 + 2u;
  TFR(13,15,26,6)  x0 += k0; x1 += k1 + 3u;
  TFR(17,29,16,24) x0 += k1; x1 += k2 + 4u;
  TFR(13,15,26,6)  x0 += k2; x1 += k0 + 5u;
  #undef TFR
  o0 = x0; o1 = x1;
}

// XLA ErfInv f32 (Giles polynomial) — matches lax.erf_inv
__device__ __forceinline__ float erfinv_f(float x){
  float w = -log1pf(-x*x);
  float p;
  if (w < 5.0f){
    w -= 2.5f;
    p = 2.81022636e-08f;
    p = fmaf(p, w, 3.43273939e-07f);
    p = fmaf(p, w, -3.5233877e-06f);
    p = fmaf(p, w, -4.39150654e-06f);
    p = fmaf(p, w, 0.00021858087f);
    p = fmaf(p, w, -0.00125372503f);
    p = fmaf(p, w, -0.00417768164f);
    p = fmaf(p, w, 0.246640727f);
    p = fmaf(p, w, 1.50140941f);
  } else {
    w = sqrtf(w) - 3.0f;
    p = -0.000200214257f;
    p = fmaf(p, w, 0.000100950558f);
    p = fmaf(p, w, 0.00134934322f);
    p = fmaf(p, w, -0.00367342844f);
    p = fmaf(p, w, 0.00573950773f);
    p = fmaf(p, w, -0.0076224613f);
    p = fmaf(p, w, 0.00943887047f);
    p = fmaf(p, w, 1.00167406f);
    p = fmaf(p, w, 2.83297682f);
  }
  return p * x;
}

// jax.random.normal: bits -> uniform(lo,1) -> sqrt(2)*erfinv
__device__ __forceinline__ float bits_to_normal(uint32_t bits){
  float f = __uint_as_float((bits >> 9) | 0x3f800000u) - 1.0f;  // [0,1)
  const float lo = -0.99999994f;                                 // nextafter(-1,0)
  float u = fmaf(f, 2.0f, lo);                                   // (1-lo) rounds to 2.0f
  u = fmaxf(u, lo);
  return 1.41421356237309515f * erfinv_f(u);
}

__device__ __forceinline__ float warpsum(float v){
  #pragma unroll
  for (int o = 16; o > 0; o >>= 1) v += __shfl_xor_sync(0xffffffffu, v, o);
  return v;
}
__device__ __forceinline__ float sigmoidf_(float x){ return 1.0f/(1.0f + expf(-x)); }

// ---------------- mega kernel: 1 block = 8 batch elems, full T loop ----------------
__global__ __launch_bounds__(256, 1)
void vkc_kernel(
  const int*   __restrict__ gesture_idx,
  const float* __restrict__ demographics,
  const float* __restrict__ emb_table,
  const float* __restrict__ dW1, const float* __restrict__ db1,
  const float* __restrict__ dW2, const float* __restrict__ db2,
  const float* __restrict__ jiW, const float* __restrict__ jib,
  const float* __restrict__ gatW, const float* __restrict__ gat_asrc,
  const float* __restrict__ gat_adst, const float* __restrict__ gat_b,
  const float* __restrict__ ln_g, const float* __restrict__ ln_b,
  const float* __restrict__ W_ih, const float* __restrict__ W_hh,
  const float* __restrict__ b_ih, const float* __restrict__ b_hh,
  const float* __restrict__ pW1, const float* __restrict__ pb1,
  const float* __restrict__ pW2, const float* __restrict__ pb2,
  const float* __restrict__ aW1, const float* __restrict__ ab1,
  const float* __restrict__ aW2, const float* __restrict__ ab2,
  const float* __restrict__ aW3, const float* __restrict__ ab3,
  float* __restrict__ out)
{
  __shared__ __align__(16) float xs[24][128];     // x state: 8 elems x 3 joints
  __shared__ __align__(16) float xp[24][128];     // GAT transformed
  __shared__ __align__(16) float hs[8][128];
  __shared__ __align__(16) float cs[8][128];
  __shared__ __align__(16) float gates[8][512];   // also comb[8][256] in setup
  __shared__ __align__(16) float scr[8][64];

  const int tid  = threadIdx.x;
  const int w    = tid >> 5;     // warp = local element
  const int lane = tid & 31;
  const int g    = blockIdx.x;
  const int b    = (w < 4) ? (4*g + w) : (512 + 4*g + (w - 4));
  const int wr   = w * 3;        // row base for this element in xs/xp
  const int col  = tid & 127;
  const int rg   = tid >> 7;     // rowgroup 0/1 for cooperative GEMMs

  // ---------------- setup: demo MLP + embedding -> combined ----------------
  {
    float dm[7];
    #pragma unroll
    for (int i = 0; i < 7; i++) dm[i] = demographics[b*7 + i];
    float a0 = db1[lane], a1 = db1[lane + 32];
    #pragma unroll
    for (int i = 0; i < 7; i++){
      a0 = fmaf(dm[i], dW1[i*64 + lane],      a0);
      a1 = fmaf(dm[i], dW1[i*64 + lane + 32], a1);
    }
    scr[w][lane]      = fmaxf(a0, 0.f);
    scr[w][lane + 32] = fmaxf(a1, 0.f);
    __syncwarp();
    const int gi = gesture_idx[b];
    #pragma unroll
    for (int q = 0; q < 4; q++){
      int c = lane + 32*q;
      gates[w][c] = emb_table[gi*128 + c];        // combined[0:128] = gesture emb
      float acc = db2[c];
      #pragma unroll 4
      for (int k = 0; k < 64; k++) acc = fmaf(scr[w][k], dW2[k*128 + c], acc);
      gates[w][128 + c] = acc;                    // combined[128:256] = demo feats
      hs[w][c] = 0.f; cs[w][c] = 0.f;
    }
  }
  __syncthreads();

  // ---------------- jf = relu(combined @ jiW + jib) -> xs ----------------
  {
    float acc[12];
    #pragma unroll
    for (int i = 0; i < 12; i++) acc[i] = 0.f;
    const int ebase = rg*4;
    #pragma unroll 4
    for (int k = 0; k < 256; k++){
      float w0 = jiW[0*32768 + k*128 + col];
      float w1 = jiW[1*32768 + k*128 + col];
      float w2 = jiW[2*32768 + k*128 + col];
      #pragma unroll
      for (int ee = 0; ee < 4; ee++){
        float cv = gates[ebase + ee][k];
        acc[ee*3+0] = fmaf(cv, w0, acc[ee*3+0]);
        acc[ee*3+1] = fmaf(cv, w1, acc[ee*3+1]);
        acc[ee*3+2] = fmaf(cv, w2, acc[ee*3+2]);
      }
    }
    #pragma unroll
    for (int ri = 0; ri < 12; ri++){
      int j = ri % 3;
      xs[rg*12 + ri][col] = fmaxf(acc[ri] + jib[j*128 + col], 0.f);
    }
  }
  __syncthreads();

  // ---------------- time loop ----------------
  for (int t = 0; t < T_STEPS; t++){
    // ===== 3 GAT layers =====
    #pragma unroll 1
    for (int l = 0; l < 3; l++){
      // cooperative GEMM: xp[24][128] = xs[24][128] @ gatW[l]
      {
        const float* Wl = gatW + l*128*128;
        float acc[12];
        #pragma unroll
        for (int i = 0; i < 12; i++) acc[i] = 0.f;
        #pragma unroll 2
        for (int k4 = 0; k4 < 128; k4 += 4){
          float wv0 = Wl[(k4+0)*128 + col];
          float wv1 = Wl[(k4+1)*128 + col];
          float wv2 = Wl[(k4+2)*128 + col];
          float wv3 = Wl[(k4+3)*128 + col];
          #pragma unroll
          for (int ri = 0; ri < 12; ri++){
            const float4 xv = *reinterpret_cast<const float4*>(&xs[rg*12 + ri][k4]);
            acc[ri] = fmaf(xv.x, wv0, fmaf(xv.y, wv1, fmaf(xv.z, wv2, fmaf(xv.w, wv3, acc[ri]))));
          }
        }
        #pragma unroll
        for (int ri = 0; ri < 12; ri++) xp[rg*12 + ri][col] = acc[ri];
      }
      __syncthreads();

      // attention per warp (element w); i=0 keeps xp[0] as-is
      {
        const float* as = gat_asrc + l*128;
        const float* ad = gat_adst + l*128;
        #pragma unroll
        for (int h = 0; h < 4; h++){
          int c = h*32 + lane;
          float x0v = xp[wr+0][c], x1v = xp[wr+1][c], x2v = xp[wr+2][c];
          float av = as[c], dv = ad[c];
          float s0 = warpsum(x0v*av);
          float s1 = warpsum(x1v*av);
          float s2 = warpsum(x2v*av);
          float d1 = warpsum(x1v*dv);
          float d2 = warpsum(x2v*dv);
          float e10 = d1+s0; e10 = e10 > 0.f ? e10 : 0.2f*e10;
          float e11 = d1+s1; e11 = e11 > 0.f ? e11 : 0.2f*e11;
          float e21 = d2+s1; e21 = e21 > 0.f ? e21 : 0.2f*e21;
          float e22 = d2+s2; e22 = e22 > 0.f ? e22 : 0.2f*e22;
          float m1 = fmaxf(e10, e11);
          float p10 = expf(e10-m1), p11 = expf(e11-m1);
          float i1 = 1.f/(p10+p11);
          float m2 = fmaxf(e21, e22);
          float p21 = expf(e21-m2), p22 = expf(e22-m2);
          float i2 = 1.f/(p21+p22);
          xp[wr+1][c] = (p10*x0v + p11*x1v)*i1;
          xp[wr+2][c] = (p21*x1v + p22*x2v)*i2;
        }
        // bias + layernorm + relu + residual (rows j=0..2)
        #pragma unroll
        for (int j = 0; j < 3; j++){
          float v[4];
          #pragma unroll
          for (int q = 0; q < 4; q++){
            int c = lane + 32*q;
            v[q] = xp[wr+j][c] + gat_b[l*128 + c];
          }
          float mu = warpsum(v[0]+v[1]+v[2]+v[3]) * (1.f/128.f);
          float vs = 0.f;
          #pragma unroll
          for (int q = 0; q < 4; q++){ float d = v[q]-mu; vs = fmaf(d, d, vs); }
          float inv = rsqrtf(warpsum(vs)*(1.f/128.f) + 1e-5f);
          #pragma unroll
          for (int q = 0; q < 4; q++){
            int c = lane + 32*q;
            float y = (v[q]-mu)*inv*ln_g[l*128 + c] + ln_b[l*128 + c];
            xs[wr+j][c] = fmaxf(y, 0.f) + xs[wr+j][c];
          }
        }
      }
      __syncthreads();
    }

    // ===== LSTM gates GEMM: gates[8][512] = w@W_ih + h@W_hh =====
    {
      const int c  = tid;
      const int c2 = tid + 256;
      float acc[8][2];
      #pragma unroll
      for (int e = 0; e < 8; e++){ acc[e][0] = 0.f; acc[e][1] = 0.f; }
      #pragma unroll 2
      for (int k4 = 0; k4 < 128; k4 += 4){
        float wia[4], wib[4], wha[4], whb[4];
        #pragma unroll
        for (int i = 0; i < 4; i++){
          wia[i] = W_ih[(k4+i)*512 + c];
          wib[i] = W_ih[(k4+i)*512 + c2];
          wha[i] = W_hh[(k4+i)*512 + c];
          whb[i] = W_hh[(k4+i)*512 + c2];
        }
        #pragma unroll
        for (int e = 0; e < 8; e++){
          const float4 xv = *reinterpret_cast<const float4*>(&xs[e*3+2][k4]);
          const float4 hv = *reinterpret_cast<const float4*>(&hs[e][k4]);
          float a0 = acc[e][0], a1 = acc[e][1];
          a0 = fmaf(xv.x, wia[0], a0); a0 = fmaf(xv.y, wia[1], a0);
          a0 = fmaf(xv.z, wia[2], a0); a0 = fmaf(xv.w, wia[3], a0);
          a0 = fmaf(hv.x, wha[0], a0); a0 = fmaf(hv.y, wha[1], a0);
          a0 = fmaf(hv.z, wha[2], a0); a0 = fmaf(hv.w, wha[3], a0);
          a1 = fmaf(xv.x, wib[0], a1); a1 = fmaf(xv.y, wib[1], a1);
          a1 = fmaf(xv.z, wib[2], a1); a1 = fmaf(xv.w, wib[3], a1);
          a1 = fmaf(hv.x, whb[0], a1); a1 = fmaf(hv.y, whb[1], a1);
          a1 = fmaf(hv.z, whb[2], a1); a1 = fmaf(hv.w, whb[3], a1);
          acc[e][0] = a0; acc[e][1] = a1;
        }
      }
      #pragma unroll
      for (int e = 0; e < 8; e++){
        gates[e][c]  = acc[e][0];
        gates[e][c2] = acc[e][1];
      }
    }
    __syncthreads();

    // ===== per-warp: LSTM pointwise + output heads =====
    {
      #pragma unroll
      for (int q = 0; q < 4; q++){
        int cx = lane + 32*q;
        float gi = gates[w][cx]       + b_ih[cx]       + b_hh[cx];
        float gf = gates[w][128 + cx] + b_ih[128 + cx] + b_hh[128 + cx];
        float gg = gates[w][256 + cx] + b_ih[256 + cx] + b_hh[256 + cx];
        float go = gates[w][384 + cx] + b_ih[384 + cx] + b_hh[384 + cx];
        float cn = sigmoidf_(gf)*cs[w][cx] + sigmoidf_(gi)*tanhf(gg);
        float hn = sigmoidf_(go)*tanhf(cn);
        cs[w][cx] = cn; hs[w][cx] = hn;
      }
      __syncwarp();
      // heads: p1/a1 (128->64 each)
      float p_a = pb1[lane], p_b = pb1[lane+32];
      float a_a = ab1[lane], a_b = ab1[lane+32];
      #pragma unroll 4
      for (int k = 0; k < 128; k++){
        float hv = hs[w][k];
        p_a = fmaf(hv, pW1[k*64 + lane],      p_a);
        p_b = fmaf(hv, pW1[k*64 + lane + 32], p_b);
        a_a = fmaf(hv, aW1[k*64 + lane],      a_a);
        a_b = fmaf(hv, aW1[k*64 + lane + 32], a_b);
      }
      p_a = fmaxf(p_a, 0.f); p_b = fmaxf(p_b, 0.f);
      a_a = fmaxf(a_a, 0.f); a_b = fmaxf(a_b, 0.f);
      // phys = relu(.)@pW2 + pb2
      float phys0 = warpsum(p_a*pW2[lane*3+0] + p_b*pW2[(lane+32)*3+0]) + pb2[0];
      float phys1 = warpsum(p_a*pW2[lane*3+1] + p_b*pW2[(lane+32)*3+1]) + pb2[1];
      float phys2 = warpsum(p_a*pW2[lane*3+2] + p_b*pW2[(lane+32)*3+2]) + pb2[2];
      // a2 (64->32)
      scr[w][lane] = a_a; scr[w][lane+32] = a_b;
      __syncwarp();
      float t2 = ab2[lane];
      #pragma unroll 4
      for (int k = 0; k < 64; k++) t2 = fmaf(scr[w][k], aW2[k*32 + lane], t2);
      t2 = fmaxf(t2, 0.f);
      // a3 (32->3) + combine
      float av0 = warpsum(t2*aW3[lane*3+0]) + ab3[0] + 0.1f*phys0;
      float av1 = warpsum(t2*aW3[lane*3+1]) + ab3[1] + 0.1f*phys1;
      float av2 = warpsum(t2*aW3[lane*3+2]) + ab3[2] + 0.1f*phys2;
      if (lane < 3){
        float v = (lane == 0) ? av0 : ((lane == 1) ? av1 : av2);
        out[(b*T_STEPS + t)*3 + lane] = v;
      }
    }

    // ===== noise: x += 0.05 * normal * (t/64); skip t=0 (scale 0) and t=63 (carry unused)
    // JAX >= 0.5 default: threefry_partitionable -> counter = flat index (hi=0, lo=m),
    // 32-bit bits = o0 ^ o1, one threefry per element.
    if (t >= 1 && t < T_STEPS - 1){
      const float scale = 0.05f * (float)t * (1.0f/64.0f);
      uint32_t kt0, kt1;
      threefry(0u, 42u, 0u, (uint32_t)t, kt0, kt1);   // fold_in(key(42), t)
      #pragma unroll 1
      for (int ii = tid; ii < 3072; ii += 256){
        int e   = ii / 384;          // local element 0..7
        int idx = ii - e*384;        // j*128 + k
        int bb  = (e < 4) ? (4*g + e) : (512 + 4*g + (e - 4));
        uint32_t m = (uint32_t)(bb*384 + idx);
        uint32_t o0, o1;
        threefry(kt0, kt1, 0u, m, o0, o1);
        xs[e*3 + (idx >> 7)][idx & 127] += scale * bits_to_normal(o0 ^ o1);
      }
    }
    __syncthreads();
  }
}

extern "C" void kernel_launch(void* const* d_in, const int* in_sizes, int n_in,
                              void* d_out, int out_size)
{
  // input order per setup_inputs; sequence_length (scalar) may or may not be
  // materialized as an input tensor — detect via count.
  const int off = (n_in >= 30) ? 1 : 0;  // 1 if sequence_length present at idx 2
  const int*   gesture_idx  = (const int*)  d_in[0];
  const float* demographics = (const float*)d_in[1];
  const float* emb_table = (const float*)d_in[2 + off];
  const float* dW1  = (const float*)d_in[3 + off];
  const float* db1  = (const float*)d_in[4 + off];
  const float* dW2  = (const float*)d_in[5 + off];
  const float* db2  = (const float*)d_in[6 + off];
  const float* jiW  = (const float*)d_in[7 + off];
  const float* jib  = (const float*)d_in[8 + off];
  const float* gatW = (const float*)d_in[9 + off];
  const float* gat_asrc = (const float*)d_in[10 + off];
  const float* gat_adst = (const float*)d_in[11 + off];
  const float* gat_b    = (const float*)d_in[12 + off];
  const float* ln_g = (const float*)d_in[13 + off];
  const float* ln_b = (const float*)d_in[14 + off];
  const float* W_ih = (const float*)d_in[15 + off];
  const float* W_hh = (const float*)d_in[16 + off];
  const float* b_ih = (const float*)d_in[17 + off];
  const float* b_hh = (const float*)d_in[18 + off];
  const float* pW1  = (const float*)d_in[19 + off];
  const float* pb1  = (const float*)d_in[20 + off];
  const float* pW2  = (const float*)d_in[21 + off];
  const float* pb2  = (const float*)d_in[22 + off];
  const float* aW1  = (const float*)d_in[23 + off];
  const float* ab1  = (const float*)d_in[24 + off];
  const float* aW2  = (const float*)d_in[25 + off];
  const float* ab2  = (const float*)d_in[26 + off];
  const float* aW3  = (const float*)d_in[27 + off];
  const float* ab3  = (const float*)d_in[28 + off];

  vkc_kernel<<<128, 256>>>(gesture_idx, demographics, emb_table,
                           dW1, db1, dW2, db2, jiW, jib,
                           gatW, gat_asrc, gat_adst, gat_b, ln_g, ln_b,
                           W_ih, W_hh, b_ih, b_hh,
                           pW1, pb1, pW2, pb2,
                           aW1, ab1, aW2, ab2, aW3, ab3,
                           (float*)d_out);
}

// round 4
// speedup vs baseline: 1.1344x; 1.1344x over previous
#include <cuda_runtime.h>
#include <cstdint>

#define T_STEPS 64

// ---------------- threefry2x32 (exact JAX, partitionable path) ----------------
__device__ __forceinline__ uint32_t rotl32(uint32_t x, int d){ return __funnelshift_l(x, x, d); }

__device__ __forceinline__ void threefry(uint32_t k0, uint32_t k1, uint32_t x0, uint32_t x1,
                                         uint32_t& o0, uint32_t& o1){
  uint32_t k2 = k0 ^ k1 ^ 0x1BD11BDAu;
  x0 += k0; x1 += k1;
  #define TFR(a,b,c,d) \
    x0 += x1; x1 = rotl32(x1,a); x1 ^= x0; \
    x0 += x1; x1 = rotl32(x1,b); x1 ^= x0; \
    x0 += x1; x1 = rotl32(x1,c); x1 ^= x0; \
    x0 += x1; x1 = rotl32(x1,d); x1 ^= x0;
  TFR(13,15,26,6)  x0 += k1; x1 += k2 + 1u;
  TFR(17,29,16,24) x0 += k2; x1 += k0 + 2u;
  TFR(13,15,26,6)  x0 += k0; x1 += k1 + 3u;
  TFR(17,29,16,24) x0 += k1; x1 += k2 + 4u;
  TFR(13,15,26,6)  x0 += k2; x1 += k0 + 5u;
  #undef TFR
  o0 = x0; o1 = x1;
}

// XLA ErfInv f32 (Giles polynomial)
__device__ __forceinline__ float erfinv_f(float x){
  float w = -log1pf(-x*x);
  float p;
  if (w < 5.0f){
    w -= 2.5f;
    p = 2.81022636e-08f;
    p = fmaf(p, w, 3.43273939e-07f);
    p = fmaf(p, w, -3.5233877e-06f);
    p = fmaf(p, w, -4.39150654e-06f);
    p = fmaf(p, w, 0.00021858087f);
    p = fmaf(p, w, -0.00125372503f);
    p = fmaf(p, w, -0.00417768164f);
    p = fmaf(p, w, 0.246640727f);
    p = fmaf(p, w, 1.50140941f);
  } else {
    w = sqrtf(w) - 3.0f;
    p = -0.000200214257f;
    p = fmaf(p, w, 0.000100950558f);
    p = fmaf(p, w, 0.00134934322f);
    p = fmaf(p, w, -0.00367342844f);
    p = fmaf(p, w, 0.00573950773f);
    p = fmaf(p, w, -0.0076224613f);
    p = fmaf(p, w, 0.00943887047f);
    p = fmaf(p, w, 1.00167406f);
    p = fmaf(p, w, 2.83297682f);
  }
  return p * x;
}

__device__ __forceinline__ float bits_to_normal(uint32_t bits){
  float f = __uint_as_float((bits >> 9) | 0x3f800000u) - 1.0f;
  const float lo = -0.99999994f;
  float u = fmaf(f, 2.0f, lo);
  u = fmaxf(u, lo);
  return 1.41421356237309515f * erfinv_f(u);
}

__device__ __forceinline__ float warpsum(float v){
  #pragma unroll
  for (int o = 16; o > 0; o >>= 1) v += __shfl_xor_sync(0xffffffffu, v, o);
  return v;
}
__device__ __forceinline__ float sigmoidf_(float x){ return 1.0f/(1.0f + expf(-x)); }

// ---------------- mega kernel: 1 block = 4 batch elems, 2 warps/elem, 2 CTA/SM ----------------
__global__ __launch_bounds__(256, 2)
void vkc_kernel(
  const int*   __restrict__ gesture_idx,
  const float* __restrict__ demographics,
  const float* __restrict__ emb_table,
  const float* __restrict__ dW1, const float* __restrict__ db1,
  const float* __restrict__ dW2, const float* __restrict__ db2,
  const float* __restrict__ jiW, const float* __restrict__ jib,
  const float* __restrict__ gatW, const float* __restrict__ gat_asrc,
  const float* __restrict__ gat_adst, const float* __restrict__ gat_b,
  const float* __restrict__ ln_g, const float* __restrict__ ln_b,
  const float* __restrict__ W_ih, const float* __restrict__ W_hh,
  const float* __restrict__ b_ih, const float* __restrict__ b_hh,
  const float* __restrict__ pW1, const float* __restrict__ pb1,
  const float* __restrict__ pW2, const float* __restrict__ pb2,
  const float* __restrict__ aW1, const float* __restrict__ ab1,
  const float* __restrict__ aW2, const float* __restrict__ ab2,
  const float* __restrict__ aW3, const float* __restrict__ ab3,
  float* __restrict__ out)
{
  __shared__ __align__(16) float xs[12][128];     // x state: 4 elems x 3 joints
  __shared__ __align__(16) float xp[12][128];     // GAT transformed
  __shared__ __align__(16) float hs[4][128];
  __shared__ __align__(16) float cs[4][128];
  __shared__ __align__(16) float gates[4][512];   // also comb[4][256] in setup
  __shared__ __align__(16) float scr[4][64];
  __shared__              float physs[4][3];

  const int tid  = threadIdx.x;
  const int w    = tid >> 5;     // warp 0..7
  const int lane = tid & 31;
  const int e    = w >> 1;       // local element 0..3
  const int wh   = w & 1;        // warp-half within element
  const int g    = blockIdx.x;   // 0..255
  const int b    = g*4 + e;
  const int wr   = e * 3;        // row base in xs/xp
  const int col  = tid & 127;
  const int rg   = tid >> 7;     // rowgroup 0/1 for cooperative GEMMs

  // ---------------- setup: demo MLP + embedding -> combined ----------------
  {
    float dm[7];
    #pragma unroll
    for (int i = 0; i < 7; i++) dm[i] = demographics[b*7 + i];
    int d = wh*32 + lane;                 // this warp's 32 hidden dims
    float a0 = db1[d];
    #pragma unroll
    for (int i = 0; i < 7; i++) a0 = fmaf(dm[i], dW1[i*64 + d], a0);
    scr[e][d] = fmaxf(a0, 0.f);
  }
  __syncthreads();
  {
    const int gi = gesture_idx[b];
    #pragma unroll
    for (int q = 0; q < 2; q++){
      int c = wh*64 + 32*q + lane;        // 0..127 split across 2 warps
      gates[e][c] = emb_table[gi*128 + c];
      float acc = db2[c];
      #pragma unroll 4
      for (int k = 0; k < 64; k++) acc = fmaf(scr[e][k], dW2[k*128 + c], acc);
      gates[e][128 + c] = acc;
      hs[e][c] = 0.f; cs[e][c] = 0.f;
    }
  }
  __syncthreads();

  // ---------------- jf = relu(combined @ jiW + jib) -> xs ----------------
  {
    float acc[6];
    #pragma unroll
    for (int i = 0; i < 6; i++) acc[i] = 0.f;
    const int ebase = rg*2;               // elements {0,1} or {2,3}
    #pragma unroll 4
    for (int k = 0; k < 256; k++){
      float w0 = jiW[0*32768 + k*128 + col];
      float w1 = jiW[1*32768 + k*128 + col];
      float w2 = jiW[2*32768 + k*128 + col];
      #pragma unroll
      for (int ee = 0; ee < 2; ee++){
        float cv = gates[ebase + ee][k];
        acc[ee*3+0] = fmaf(cv, w0, acc[ee*3+0]);
        acc[ee*3+1] = fmaf(cv, w1, acc[ee*3+1]);
        acc[ee*3+2] = fmaf(cv, w2, acc[ee*3+2]);
      }
    }
    #pragma unroll
    for (int ri = 0; ri < 6; ri++){
      int j = ri % 3;
      xs[rg*6 + ri][col] = fmaxf(acc[ri] + jib[j*128 + col], 0.f);
    }
  }
  __syncthreads();

  // ---------------- time loop ----------------
  for (int t = 0; t < T_STEPS; t++){
    // ===== 3 GAT layers =====
    #pragma unroll 1
    for (int l = 0; l < 3; l++){
      // cooperative GEMM: xp[12][128] = xs[12][128] @ gatW[l]
      {
        const float* Wl = gatW + l*128*128;
        float acc[6];
        #pragma unroll
        for (int i = 0; i < 6; i++) acc[i] = 0.f;
        #pragma unroll 2
        for (int k4 = 0; k4 < 128; k4 += 4){
          float wv0 = Wl[(k4+0)*128 + col];
          float wv1 = Wl[(k4+1)*128 + col];
          float wv2 = Wl[(k4+2)*128 + col];
          float wv3 = Wl[(k4+3)*128 + col];
          #pragma unroll
          for (int ri = 0; ri < 6; ri++){
            const float4 xv = *reinterpret_cast<const float4*>(&xs[rg*6 + ri][k4]);
            acc[ri] = fmaf(xv.x, wv0, fmaf(xv.y, wv1, fmaf(xv.z, wv2, fmaf(xv.w, wv3, acc[ri]))));
          }
        }
        #pragma unroll
        for (int ri = 0; ri < 6; ri++) xp[rg*6 + ri][col] = acc[ri];
      }
      __syncthreads();

      // attention: 2 heads per warp (heads 2*wh, 2*wh+1)
      {
        const float* as = gat_asrc + l*128;
        const float* ad = gat_adst + l*128;
        #pragma unroll
        for (int hh = 0; hh < 2; hh++){
          int h = 2*wh + hh;
          int c = h*32 + lane;
          float x0v = xp[wr+0][c], x1v = xp[wr+1][c], x2v = xp[wr+2][c];
          float av = as[c], dv = ad[c];
          float s0 = warpsum(x0v*av);
          float s1 = warpsum(x1v*av);
          float s2 = warpsum(x2v*av);
          float d1 = warpsum(x1v*dv);
          float d2 = warpsum(x2v*dv);
          float e10 = d1+s0; e10 = e10 > 0.f ? e10 : 0.2f*e10;
          float e11 = d1+s1; e11 = e11 > 0.f ? e11 : 0.2f*e11;
          float e21 = d2+s1; e21 = e21 > 0.f ? e21 : 0.2f*e21;
          float e22 = d2+s2; e22 = e22 > 0.f ? e22 : 0.2f*e22;
          float m1 = fmaxf(e10, e11);
          float p10 = expf(e10-m1), p11 = expf(e11-m1);
          float i1 = 1.f/(p10+p11);
          float m2 = fmaxf(e21, e22);
          float p21 = expf(e21-m2), p22 = expf(e22-m2);
          float i2 = 1.f/(p21+p22);
          xp[wr+1][c] = (p10*x0v + p11*x1v)*i1;
          xp[wr+2][c] = (p21*x1v + p22*x2v)*i2;
        }
      }
      __syncthreads();

      // bias + layernorm + relu + residual; rows: wh0 -> j=0,2 ; wh1 -> j=1
      {
        #pragma unroll
        for (int jj = 0; jj < 2; jj++){
          int j = (wh == 0) ? (jj == 0 ? 0 : 2) : 1;
          if (wh == 1 && jj == 1) break;
          float v[4];
          #pragma unroll
          for (int q = 0; q < 4; q++){
            int c = lane + 32*q;
            v[q] = xp[wr+j][c] + gat_b[l*128 + c];
          }
          float mu = warpsum(v[0]+v[1]+v[2]+v[3]) * (1.f/128.f);
          float vs = 0.f;
          #pragma unroll
          for (int q = 0; q < 4; q++){ float d = v[q]-mu; vs = fmaf(d, d, vs); }
          float inv = rsqrtf(warpsum(vs)*(1.f/128.f) + 1e-5f);
          #pragma unroll
          for (int q = 0; q < 4; q++){
            int c = lane + 32*q;
            float y = (v[q]-mu)*inv*ln_g[l*128 + c] + ln_b[l*128 + c];
            xs[wr+j][c] = fmaxf(y, 0.f) + xs[wr+j][c];
          }
        }
      }
      __syncthreads();
    }

    // ===== LSTM gates GEMM: gates[4][512] = w@W_ih + h@W_hh =====
    {
      const int c  = tid;
      const int c2 = tid + 256;
      float acc[4][2];
      #pragma unroll
      for (int ee = 0; ee < 4; ee++){ acc[ee][0] = 0.f; acc[ee][1] = 0.f; }
      #pragma unroll 2
      for (int k4 = 0; k4 < 128; k4 += 4){
        float wia[4], wib[4], wha[4], whb[4];
        #pragma unroll
        for (int i = 0; i < 4; i++){
          wia[i] = W_ih[(k4+i)*512 + c];
          wib[i] = W_ih[(k4+i)*512 + c2];
          wha[i] = W_hh[(k4+i)*512 + c];
          whb[i] = W_hh[(k4+i)*512 + c2];
        }
        #pragma unroll
        for (int ee = 0; ee < 4; ee++){
          const float4 xv = *reinterpret_cast<const float4*>(&xs[ee*3+2][k4]);
          const float4 hv = *reinterpret_cast<const float4*>(&hs[ee][k4]);
          float a0 = acc[ee][0], a1 = acc[ee][1];
          a0 = fmaf(xv.x, wia[0], a0); a0 = fmaf(xv.y, wia[1], a0);
          a0 = fmaf(xv.z, wia[2], a0); a0 = fmaf(xv.w, wia[3], a0);
          a0 = fmaf(hv.x, wha[0], a0); a0 = fmaf(hv.y, wha[1], a0);
          a0 = fmaf(hv.z, wha[2], a0); a0 = fmaf(hv.w, wha[3], a0);
          a1 = fmaf(xv.x, wib[0], a1); a1 = fmaf(xv.y, wib[1], a1);
          a1 = fmaf(xv.z, wib[2], a1); a1 = fmaf(xv.w, wib[3], a1);
          a1 = fmaf(hv.x, whb[0], a1); a1 = fmaf(hv.y, whb[1], a1);
          a1 = fmaf(hv.z, whb[2], a1); a1 = fmaf(hv.w, whb[3], a1);
          acc[ee][0] = a0; acc[ee][1] = a1;
        }
      }
      #pragma unroll
      for (int ee = 0; ee < 4; ee++){
        gates[ee][c]  = acc[ee][0];
        gates[ee][c2] = acc[ee][1];
      }
    }
    __syncthreads();

    // ===== LSTM pointwise: each warp handles 2 of 4 q-chunks =====
    {
      #pragma unroll
      for (int qq = 0; qq < 2; qq++){
        int cx = lane + 32*(2*wh + qq);
        float gi = gates[e][cx]       + b_ih[cx]       + b_hh[cx];
        float gf = gates[e][128 + cx] + b_ih[128 + cx] + b_hh[128 + cx];
        float gg = gates[e][256 + cx] + b_ih[256 + cx] + b_hh[256 + cx];
        float go = gates[e][384 + cx] + b_ih[384 + cx] + b_hh[384 + cx];
        float cn = sigmoidf_(gf)*cs[e][cx] + sigmoidf_(gi)*tanhf(gg);
        float hn = sigmoidf_(go)*tanhf(cn);
        cs[e][cx] = cn; hs[e][cx] = hn;
      }
    }
    __syncthreads();

    // ===== output heads: wh0 = phys path, wh1 = act path =====
    if (wh == 0){
      float p_a = pb1[lane], p_b = pb1[lane+32];
      #pragma unroll 4
      for (int k = 0; k < 128; k++){
        float hv = hs[e][k];
        p_a = fmaf(hv, pW1[k*64 + lane],      p_a);
        p_b = fmaf(hv, pW1[k*64 + lane + 32], p_b);
      }
      p_a = fmaxf(p_a, 0.f); p_b = fmaxf(p_b, 0.f);
      float phys0 = warpsum(p_a*pW2[lane*3+0] + p_b*pW2[(lane+32)*3+0]) + pb2[0];
      float phys1 = warpsum(p_a*pW2[lane*3+1] + p_b*pW2[(lane+32)*3+1]) + pb2[1];
      float phys2 = warpsum(p_a*pW2[lane*3+2] + p_b*pW2[(lane+32)*3+2]) + pb2[2];
      if (lane == 0){ physs[e][0] = phys0; physs[e][1] = phys1; physs[e][2] = phys2; }
    } else {
      float a_a = ab1[lane], a_b = ab1[lane+32];
      #pragma unroll 4
      for (int k = 0; k < 128; k++){
        float hv = hs[e][k];
        a_a = fmaf(hv, aW1[k*64 + lane],      a_a);
        a_b = fmaf(hv, aW1[k*64 + lane + 32], a_b);
      }
      a_a = fmaxf(a_a, 0.f); a_b = fmaxf(a_b, 0.f);
      scr[e][lane] = a_a; scr[e][lane+32] = a_b;
      __syncwarp();
      float t2 = ab2[lane];
      #pragma unroll 4
      for (int k = 0; k < 64; k++) t2 = fmaf(scr[e][k], aW2[k*32 + lane], t2);
      t2 = fmaxf(t2, 0.f);
      scr[e][lane] = t2;   // stash for after sync
    }
    __syncthreads();

    if (wh == 1){
      float t2 = scr[e][lane];
      float av0 = warpsum(t2*aW3[lane*3+0]) + ab3[0] + 0.1f*physs[e][0];
      float av1 = warpsum(t2*aW3[lane*3+1]) + ab3[1] + 0.1f*physs[e][1];
      float av2 = warpsum(t2*aW3[lane*3+2]) + ab3[2] + 0.1f*physs[e][2];
      if (lane < 3){
        float v = (lane == 0) ? av0 : ((lane == 1) ? av1 : av2);
        out[(b*T_STEPS + t)*3 + lane] = v;
      }
    }

    // ===== noise: x += 0.05 * normal * (t/64); skip t=0 (scale 0) and t=63 (carry unused)
    if (t >= 1 && t < T_STEPS - 1){
      const float scale = 0.05f * (float)t * (1.0f/64.0f);
      uint32_t kt0, kt1;
      threefry(0u, 42u, 0u, (uint32_t)t, kt0, kt1);   // fold_in(key(42), t)
      #pragma unroll 1
      for (int ii = tid; ii < 1536; ii += 256){
        int ee  = ii / 384;          // local element 0..3
        int idx = ii - ee*384;       // j*128 + k
        uint32_t m = (uint32_t)((g*4 + ee)*384 + idx);
        uint32_t o0, o1;
        threefry(kt0, kt1, 0u, m, o0, o1);
        xs[ee*3 + (idx >> 7)][idx & 127] += scale * bits_to_normal(o0 ^ o1);
      }
    }
    __syncthreads();
  }
}

extern "C" void kernel_launch(void* const* d_in, const int* in_sizes, int n_in,
                              void* d_out, int out_size)
{
  const int off = (n_in >= 30) ? 1 : 0;  // 1 if sequence_length present at idx 2
  const int*   gesture_idx  = (const int*)  d_in[0];
  const float* demographics = (const float*)d_in[1];
  const float* emb_table = (const float*)d_in[2 + off];
  const float* dW1  = (const float*)d_in[3 + off];
  const float* db1  = (const float*)d_in[4 + off];
  const float* dW2  = (const float*)d_in[5 + off];
  const float* db2  = (const float*)d_in[6 + off];
  const float* jiW  = (const float*)d_in[7 + off];
  const float* jib  = (const float*)d_in[8 + off];
  const float* gatW = (const float*)d_in[9 + off];
  const float* gat_asrc = (const float*)d_in[10 + off];
  const float* gat_adst = (const float*)d_in[11 + off];
  const float* gat_b    = (const float*)d_in[12 + off];
  const float* ln_g = (const float*)d_in[13 + off];
  const float* ln_b = (const float*)d_in[14 + off];
  const float* W_ih = (const float*)d_in[15 + off];
  const float* W_hh = (const float*)d_in[16 + off];
  const float* b_ih = (const float*)d_in[17 + off];
  const float* b_hh = (const float*)d_in[18 + off];
  const float* pW1  = (const float*)d_in[19 + off];
  const float* pb1  = (const float*)d_in[20 + off];
  const float* pW2  = (const float*)d_in[21 + off];
  const float* pb2  = (const float*)d_in[22 + off];
  const float* aW1  = (const float*)d_in[23 + off];
  const float* ab1  = (const float*)d_in[24 + off];
  const float* aW2  = (const float*)d_in[25 + off];
  const float* ab2  = (const float*)d_in[26 + off];
  const float* aW3  = (const float*)d_in[27 + off];
  const float* ab3  = (const float*)d_in[28 + off];

  vkc_kernel<<<256, 256>>>(gesture_idx, demographics, emb_table,
                           dW1, db1, dW2, db2, jiW, jib,
                           gatW, gat_asrc, gat_adst, gat_b, ln_g, ln_b,
                           W_ih, W_hh, b_ih, b_hh,
                           pW1, pb1, pW2, pb2,
                           aW1, ab1, aW2, ab2, aW3, ab3,
                           (float*)d_out);
}

// round 5
// speedup vs baseline: 1.4988x; 1.3213x over previous
#include <cuda_runtime.h>
#include <cstdint>

#define T_STEPS 64
typedef unsigned long long u64;

// ---------------- packed f32x2 helpers ----------------
__device__ __forceinline__ u64 ffma2(u64 a, u64 b, u64 c){
  u64 d; asm("fma.rn.f32x2 %0, %1, %2, %3;" : "=l"(d) : "l"(a), "l"(b), "l"(c)); return d;
}
__device__ __forceinline__ float hsum2(u64 a){
  return __uint_as_float((unsigned)a) + __uint_as_float((unsigned)(a >> 32));
}

#define BAR_ELEM(e) asm volatile("bar.sync %0, 64;" :: "r"((e)+1) : "memory")

// ---------------- repacked weights (loop-invariant, built by pre-kernel) ----------------
__device__ __align__(16) float gatP[49152];   // [l][k4][c][4] : gatW[l][4k4+i][c]
__device__ __align__(16) float WihP[65536];   // [k4][c][4]
__device__ __align__(16) float WhhP[65536];
__device__ __align__(16) float pW1P[8192];
__device__ __align__(16) float aW1P[8192];
__device__ __align__(16) float aW2P[2048];

__global__ void repack_kernel(const float* __restrict__ gatW, const float* __restrict__ W_ih,
                              const float* __restrict__ W_hh, const float* __restrict__ pW1,
                              const float* __restrict__ aW1,  const float* __restrict__ aW2){
  for (int idx = blockIdx.x*blockDim.x + threadIdx.x; idx < 198656; idx += gridDim.x*blockDim.x){
    if (idx < 49152){
      int f = idx; int i = f&3, c = (f>>2)&127, k4 = (f>>9)&31, l = f>>14;
      gatP[f] = gatW[(l*128 + k4*4 + i)*128 + c];
    } else if (idx < 114688){
      int f = idx - 49152; int i = f&3, c = (f>>2)&511, k4 = f>>11;
      WihP[f] = W_ih[(k4*4+i)*512 + c];
    } else if (idx < 180224){
      int f = idx - 114688; int i = f&3, c = (f>>2)&511, k4 = f>>11;
      WhhP[f] = W_hh[(k4*4+i)*512 + c];
    } else if (idx < 188416){
      int f = idx - 180224; int i = f&3, c = (f>>2)&63, k4 = f>>8;
      pW1P[f] = pW1[(k4*4+i)*64 + c];
    } else if (idx < 196608){
      int f = idx - 188416; int i = f&3, c = (f>>2)&63, k4 = f>>8;
      aW1P[f] = aW1[(k4*4+i)*64 + c];
    } else {
      int f = idx - 196608; int i = f&3, c = (f>>2)&31, k4 = f>>7;
      aW2P[f] = aW2[(k4*4+i)*32 + c];
    }
  }
}

// ---------------- threefry2x32 (exact JAX, partitionable path) ----------------
__device__ __forceinline__ uint32_t rotl32(uint32_t x, int d){ return __funnelshift_l(x, x, d); }

__device__ __forceinline__ void threefry(uint32_t k0, uint32_t k1, uint32_t x0, uint32_t x1,
                                         uint32_t& o0, uint32_t& o1){
  uint32_t k2 = k0 ^ k1 ^ 0x1BD11BDAu;
  x0 += k0; x1 += k1;
  #define TFR(a,b,c,d) \
    x0 += x1; x1 = rotl32(x1,a); x1 ^= x0; \
    x0 += x1; x1 = rotl32(x1,b); x1 ^= x0; \
    x0 += x1; x1 = rotl32(x1,c); x1 ^= x0; \
    x0 += x1; x1 = rotl32(x1,d); x1 ^= x0;
  TFR(13,15,26,6)  x0 += k1; x1 += k2 + 1u;
  TFR(17,29,16,24) x0 += k2; x1 += k0 + 2u;
  TFR(13,15,26,6)  x0 += k0; x1 += k1 + 3u;
  TFR(17,29,16,24) x0 += k1; x1 += k2 + 4u;
  TFR(13,15,26,6)  x0 += k2; x1 += k0 + 5u;
  #undef TFR
  o0 = x0; o1 = x1;
}

// XLA ErfInv f32 (Giles polynomial); -log1p(-x^2) via fma+__logf (exact cancellation-free)
__device__ __forceinline__ float erfinv_f(float x){
  float w = -__logf(fmaf(-x, x, 1.0f));
  float p;
  if (w < 5.0f){
    w -= 2.5f;
    p = 2.81022636e-08f;
    p = fmaf(p, w, 3.43273939e-07f);
    p = fmaf(p, w, -3.5233877e-06f);
    p = fmaf(p, w, -4.39150654e-06f);
    p = fmaf(p, w, 0.00021858087f);
    p = fmaf(p, w, -0.00125372503f);
    p = fmaf(p, w, -0.00417768164f);
    p = fmaf(p, w, 0.246640727f);
    p = fmaf(p, w, 1.50140941f);
  } else {
    w = sqrtf(w) - 3.0f;
    p = -0.000200214257f;
    p = fmaf(p, w, 0.000100950558f);
    p = fmaf(p, w, 0.00134934322f);
    p = fmaf(p, w, -0.00367342844f);
    p = fmaf(p, w, 0.00573950773f);
    p = fmaf(p, w, -0.0076224613f);
    p = fmaf(p, w, 0.00943887047f);
    p = fmaf(p, w, 1.00167406f);
    p = fmaf(p, w, 2.83297682f);
  }
  return p * x;
}

__device__ __forceinline__ float bits_to_normal(uint32_t bits){
  float f = __uint_as_float((bits >> 9) | 0x3f800000u) - 1.0f;
  const float lo = -0.99999994f;
  float u = fmaf(f, 2.0f, lo);
  u = fmaxf(u, lo);
  return 1.41421356237309515f * erfinv_f(u);
}

__device__ __forceinline__ float warpsum(float v){
  #pragma unroll
  for (int o = 16; o > 0; o >>= 1) v += __shfl_xor_sync(0xffffffffu, v, o);
  return v;
}
__device__ __forceinline__ float sig_(float x){ return __frcp_rn(1.0f + __expf(-x)); }
__device__ __forceinline__ float tanh_(float x){ return fmaf(2.0f, __frcp_rn(1.0f + __expf(-2.0f*x)), -1.0f); }

// ---------------- mega kernel: 1 block = 4 batch elems, 2 warps/elem, 2 CTA/SM ----------------
__global__ __launch_bounds__(256, 2)
void vkc_kernel(
  const int*   __restrict__ gesture_idx,
  const float* __restrict__ demographics,
  const float* __restrict__ emb_table,
  const float* __restrict__ dW1, const float* __restrict__ db1,
  const float* __restrict__ dW2, const float* __restrict__ db2,
  const float* __restrict__ jiW, const float* __restrict__ jib,
  const float* __restrict__ gat_asrc,
  const float* __restrict__ gat_adst, const float* __restrict__ gat_b,
  const float* __restrict__ ln_g, const float* __restrict__ ln_b,
  const float* __restrict__ b_ih, const float* __restrict__ b_hh,
  const float* __restrict__ pb1,
  const float* __restrict__ pW2, const float* __restrict__ pb2,
  const float* __restrict__ ab1,
  const float* __restrict__ ab2,
  const float* __restrict__ aW3, const float* __restrict__ ab3,
  float* __restrict__ out)
{
  __shared__ __align__(16) float xs[12][128];     // x state: 4 elems x 3 joints
  __shared__ __align__(16) float xp[12][128];     // GAT transformed
  __shared__ __align__(16) float hs[4][128];
  __shared__ __align__(16) float cs[4][128];
  __shared__ __align__(16) float gates[4][512];   // also comb[4][256] in setup
  __shared__ __align__(16) float scr[4][64];
  __shared__              float physs[4][3];

  const int tid  = threadIdx.x;
  const int w    = tid >> 5;     // warp 0..7
  const int lane = tid & 31;
  const int e    = w >> 1;       // local element 0..3
  const int wh   = w & 1;        // warp-half within element
  const int g    = blockIdx.x;   // 0..255
  const int b    = g*4 + e;
  const int wr   = e * 3;        // row base in xs/xp
  const int col  = tid & 127;
  const int rg   = tid >> 7;     // rowgroup 0/1 for cooperative GEMMs

  // ---------------- setup: demo MLP + embedding -> combined ----------------
  {
    float dm[7];
    #pragma unroll
    for (int i = 0; i < 7; i++) dm[i] = demographics[b*7 + i];
    int d = wh*32 + lane;
    float a0 = db1[d];
    #pragma unroll
    for (int i = 0; i < 7; i++) a0 = fmaf(dm[i], dW1[i*64 + d], a0);
    scr[e][d] = fmaxf(a0, 0.f);
  }
  __syncthreads();
  {
    const int gi = gesture_idx[b];
    #pragma unroll
    for (int q = 0; q < 2; q++){
      int c = wh*64 + 32*q + lane;
      gates[e][c] = emb_table[gi*128 + c];
      float acc = db2[c];
      #pragma unroll 4
      for (int k = 0; k < 64; k++) acc = fmaf(scr[e][k], dW2[k*128 + c], acc);
      gates[e][128 + c] = acc;
      hs[e][c] = 0.f; cs[e][c] = 0.f;
    }
  }
  __syncthreads();

  // ---------------- jf = relu(combined @ jiW + jib) -> xs ----------------
  {
    float acc[6];
    #pragma unroll
    for (int i = 0; i < 6; i++) acc[i] = 0.f;
    const int ebase = rg*2;
    #pragma unroll 4
    for (int k = 0; k < 256; k++){
      float w0 = jiW[0*32768 + k*128 + col];
      float w1 = jiW[1*32768 + k*128 + col];
      float w2 = jiW[2*32768 + k*128 + col];
      #pragma unroll
      for (int ee = 0; ee < 2; ee++){
        float cv = gates[ebase + ee][k];
        acc[ee*3+0] = fmaf(cv, w0, acc[ee*3+0]);
        acc[ee*3+1] = fmaf(cv, w1, acc[ee*3+1]);
        acc[ee*3+2] = fmaf(cv, w2, acc[ee*3+2]);
      }
    }
    #pragma unroll
    for (int ri = 0; ri < 6; ri++){
      int j = ri % 3;
      xs[rg*6 + ri][col] = fmaxf(acc[ri] + jib[j*128 + col], 0.f);
    }
  }
  __syncthreads();

  // ---------------- time loop ----------------
  for (int t = 0; t < T_STEPS; t++){
    // ===== 3 GAT layers =====
    #pragma unroll 1
    for (int l = 0; l < 3; l++){
      // cooperative GEMM (f32x2, K-paired): xp[12][128] = xs @ gatW[l]
      {
        const float* Wl = gatP + l*16384;
        u64 acc[6];
        #pragma unroll
        for (int i = 0; i < 6; i++) acc[i] = 0ull;
        #pragma unroll 4
        for (int k4 = 0; k4 < 32; k4++){
          const ulonglong2 wv = *reinterpret_cast<const ulonglong2*>(Wl + (k4*128 + col)*4);
          #pragma unroll
          for (int ri = 0; ri < 6; ri++){
            const ulonglong2 xv = *reinterpret_cast<const ulonglong2*>(&xs[rg*6 + ri][k4*4]);
            acc[ri] = ffma2(xv.x, wv.x, acc[ri]);
            acc[ri] = ffma2(xv.y, wv.y, acc[ri]);
          }
        }
        #pragma unroll
        for (int ri = 0; ri < 6; ri++) xp[rg*6 + ri][col] = hsum2(acc[ri]);
      }
      __syncthreads();

      // attention: 2 heads per warp
      {
        const float* as = gat_asrc + l*128;
        const float* ad = gat_adst + l*128;
        #pragma unroll
        for (int hh = 0; hh < 2; hh++){
          int h = 2*wh + hh;
          int c = h*32 + lane;
          float x0v = xp[wr+0][c], x1v = xp[wr+1][c], x2v = xp[wr+2][c];
          float av = as[c], dv = ad[c];
          float s0 = warpsum(x0v*av);
          float s1 = warpsum(x1v*av);
          float s2 = warpsum(x2v*av);
          float d1 = warpsum(x1v*dv);
          float d2 = warpsum(x2v*dv);
          float e10 = d1+s0; e10 = e10 > 0.f ? e10 : 0.2f*e10;
          float e11 = d1+s1; e11 = e11 > 0.f ? e11 : 0.2f*e11;
          float e21 = d2+s1; e21 = e21 > 0.f ? e21 : 0.2f*e21;
          float e22 = d2+s2; e22 = e22 > 0.f ? e22 : 0.2f*e22;
          float m1 = fmaxf(e10, e11);
          float p10 = __expf(e10-m1), p11 = __expf(e11-m1);
          float i1 = __frcp_rn(p10+p11);
          float m2 = fmaxf(e21, e22);
          float p21 = __expf(e21-m2), p22 = __expf(e22-m2);
          float i2 = __frcp_rn(p21+p22);
          xp[wr+1][c] = (p10*x0v + p11*x1v)*i1;
          xp[wr+2][c] = (p21*x1v + p22*x2v)*i2;
        }
      }
      BAR_ELEM(e);

      // bias + layernorm + relu + residual; rows: wh0 -> j=0,2 ; wh1 -> j=1
      {
        #pragma unroll
        for (int jj = 0; jj < 2; jj++){
          if (wh == 1 && jj == 1) break;
          int j = (wh == 0) ? (jj == 0 ? 0 : 2) : 1;
          float v[4];
          #pragma unroll
          for (int q = 0; q < 4; q++){
            int c = lane + 32*q;
            v[q] = xp[wr+j][c] + gat_b[l*128 + c];
          }
          float mu = warpsum(v[0]+v[1]+v[2]+v[3]) * (1.f/128.f);
          float vs = 0.f;
          #pragma unroll
          for (int q = 0; q < 4; q++){ float d = v[q]-mu; vs = fmaf(d, d, vs); }
          float inv = rsqrtf(warpsum(vs)*(1.f/128.f) + 1e-5f);
          #pragma unroll
          for (int q = 0; q < 4; q++){
            int c = lane + 32*q;
            float y = (v[q]-mu)*inv*ln_g[l*128 + c] + ln_b[l*128 + c];
            xs[wr+j][c] = fmaxf(y, 0.f) + xs[wr+j][c];
          }
        }
      }
      __syncthreads();
    }

    // ===== LSTM gates GEMM (f32x2): gates[4][512] = w@W_ih + h@W_hh =====
    {
      const int c  = tid;
      const int c2 = tid + 256;
      u64 accA[4], accB[4];
      #pragma unroll
      for (int ee = 0; ee < 4; ee++){ accA[ee] = 0ull; accB[ee] = 0ull; }
      #pragma unroll 2
      for (int k4 = 0; k4 < 32; k4++){
        const ulonglong2 wiA = *reinterpret_cast<const ulonglong2*>(WihP + (k4*512 + c )*4);
        const ulonglong2 wiB = *reinterpret_cast<const ulonglong2*>(WihP + (k4*512 + c2)*4);
        const ulonglong2 whA = *reinterpret_cast<const ulonglong2*>(WhhP + (k4*512 + c )*4);
        const ulonglong2 whB = *reinterpret_cast<const ulonglong2*>(WhhP + (k4*512 + c2)*4);
        #pragma unroll
        for (int ee = 0; ee < 4; ee++){
          const ulonglong2 xv = *reinterpret_cast<const ulonglong2*>(&xs[ee*3+2][k4*4]);
          const ulonglong2 hv = *reinterpret_cast<const ulonglong2*>(&hs[ee][k4*4]);
          u64 a = accA[ee], bb = accB[ee];
          a  = ffma2(xv.x, wiA.x, a );  a  = ffma2(xv.y, wiA.y, a );
          a  = ffma2(hv.x, whA.x, a );  a  = ffma2(hv.y, whA.y, a );
          bb = ffma2(xv.x, wiB.x, bb);  bb = ffma2(xv.y, wiB.y, bb);
          bb = ffma2(hv.x, whB.x, bb);  bb = ffma2(hv.y, whB.y, bb);
          accA[ee] = a; accB[ee] = bb;
        }
      }
      #pragma unroll
      for (int ee = 0; ee < 4; ee++){
        gates[ee][c]  = hsum2(accA[ee]);
        gates[ee][c2] = hsum2(accB[ee]);
      }
    }
    __syncthreads();

    // ===== LSTM pointwise (elem warps) =====
    {
      #pragma unroll
      for (int qq = 0; qq < 2; qq++){
        int cx = lane + 32*(2*wh + qq);
        float gi = gates[e][cx]       + b_ih[cx]       + b_hh[cx];
        float gf = gates[e][128 + cx] + b_ih[128 + cx] + b_hh[128 + cx];
        float gg = gates[e][256 + cx] + b_ih[256 + cx] + b_hh[256 + cx];
        float go = gates[e][384 + cx] + b_ih[384 + cx] + b_hh[384 + cx];
        float cn = sig_(gf)*cs[e][cx] + sig_(gi)*tanh_(gg);
        float hn = sig_(go)*tanh_(cn);
        cs[e][cx] = cn; hs[e][cx] = hn;
      }
    }

    // ===== noise (overlaps: ALU pipe, xs free after gates GEMM sync) =====
    // x += 0.05 * normal * (t/64); skip t=0 (scale 0) and t=63 (carry unused)
    if (t >= 1 && t < T_STEPS - 1){
      const float scale = 0.05f * (float)t * (1.0f/64.0f);
      uint32_t kt0, kt1;
      threefry(0u, 42u, 0u, (uint32_t)t, kt0, kt1);   // fold_in(key(42), t)
      #pragma unroll 1
      for (int ii = tid; ii < 1536; ii += 256){
        int ee  = ii / 384;
        int idx = ii - ee*384;
        uint32_t m = (uint32_t)((g*4 + ee)*384 + idx);
        uint32_t o0, o1;
        threefry(kt0, kt1, 0u, m, o0, o1);
        xs[ee*3 + (idx >> 7)][idx & 127] += scale * bits_to_normal(o0 ^ o1);
      }
    }
    BAR_ELEM(e);   // hs complete within element

    // ===== output heads: wh0 = phys path, wh1 = act path =====
    float t2 = 0.f;
    if (wh == 0){
      u64 pa = 0ull, pb = 0ull;
      #pragma unroll 4
      for (int k4 = 0; k4 < 32; k4++){
        const ulonglong2 wA = *reinterpret_cast<const ulonglong2*>(pW1P + (k4*64 + lane   )*4);
        const ulonglong2 wB = *reinterpret_cast<const ulonglong2*>(pW1P + (k4*64 + lane+32)*4);
        const ulonglong2 hv = *reinterpret_cast<const ulonglong2*>(&hs[e][k4*4]);
        pa = ffma2(hv.x, wA.x, pa); pa = ffma2(hv.y, wA.y, pa);
        pb = ffma2(hv.x, wB.x, pb); pb = ffma2(hv.y, wB.y, pb);
      }
      float p_a = fmaxf(hsum2(pa) + pb1[lane],    0.f);
      float p_b = fmaxf(hsum2(pb) + pb1[lane+32], 0.f);
      float phys0 = warpsum(p_a*pW2[lane*3+0] + p_b*pW2[(lane+32)*3+0]) + pb2[0];
      float phys1 = warpsum(p_a*pW2[lane*3+1] + p_b*pW2[(lane+32)*3+1]) + pb2[1];
      float phys2 = warpsum(p_a*pW2[lane*3+2] + p_b*pW2[(lane+32)*3+2]) + pb2[2];
      if (lane == 0){ physs[e][0] = phys0; physs[e][1] = phys1; physs[e][2] = phys2; }
    } else {
      u64 aa = 0ull, ab = 0ull;
      #pragma unroll 4
      for (int k4 = 0; k4 < 32; k4++){
        const ulonglong2 wA = *reinterpret_cast<const ulonglong2*>(aW1P + (k4*64 + lane   )*4);
        const ulonglong2 wB = *reinterpret_cast<const ulonglong2*>(aW1P + (k4*64 + lane+32)*4);
        const ulonglong2 hv = *reinterpret_cast<const ulonglong2*>(&hs[e][k4*4]);
        aa = ffma2(hv.x, wA.x, aa); aa = ffma2(hv.y, wA.y, aa);
        ab = ffma2(hv.x, wB.x, ab); ab = ffma2(hv.y, wB.y, ab);
      }
      scr[e][lane]    = fmaxf(hsum2(aa) + ab1[lane],    0.f);
      scr[e][lane+32] = fmaxf(hsum2(ab) + ab1[lane+32], 0.f);
      __syncwarp();
      u64 t2a = 0ull;
      #pragma unroll
      for (int k4 = 0; k4 < 16; k4++){
        const ulonglong2 wv = *reinterpret_cast<const ulonglong2*>(aW2P + (k4*32 + lane)*4);
        const ulonglong2 sv = *reinterpret_cast<const ulonglong2*>(&scr[e][k4*4]);
        t2a = ffma2(sv.x, wv.x, t2a); t2a = ffma2(sv.y, wv.y, t2a);
      }
      t2 = fmaxf(hsum2(t2a) + ab2[lane], 0.f);
    }
    BAR_ELEM(e);

    if (wh == 1){
      float av0 = warpsum(t2*aW3[lane*3+0]) + ab3[0] + 0.1f*physs[e][0];
      float av1 = warpsum(t2*aW3[lane*3+1]) + ab3[1] + 0.1f*physs[e][1];
      float av2 = warpsum(t2*aW3[lane*3+2]) + ab3[2] + 0.1f*physs[e][2];
      if (lane < 3){
        float v = (lane == 0) ? av0 : ((lane == 1) ? av1 : av2);
        out[(b*T_STEPS + t)*3 + lane] = v;
      }
    }
    __syncthreads();   // end of step: noise xs + hs/cs stable for next iteration
  }
}

extern "C" void kernel_launch(void* const* d_in, const int* in_sizes, int n_in,
                              void* d_out, int out_size)
{
  const int off = (n_in >= 30) ? 1 : 0;  // 1 if sequence_length present at idx 2
  const int*   gesture_idx  = (const int*)  d_in[0];
  const float* demographics = (const float*)d_in[1];
  const float* emb_table = (const float*)d_in[2 + off];
  const float* dW1  = (const float*)d_in[3 + off];
  const float* db1  = (const float*)d_in[4 + off];
  const float* dW2  = (const float*)d_in[5 + off];
  const float* db2  = (const float*)d_in[6 + off];
  const float* jiW  = (const float*)d_in[7 + off];
  const float* jib  = (const float*)d_in[8 + off];
  const float* gatW = (const float*)d_in[9 + off];
  const float* gat_asrc = (const float*)d_in[10 + off];
  const float* gat_adst = (const float*)d_in[11 + off];
  const float* gat_b    = (const float*)d_in[12 + off];
  const float* ln_g = (const float*)d_in[13 + off];
  const float* ln_b = (const float*)d_in[14 + off];
  const float* W_ih = (const float*)d_in[15 + off];
  const float* W_hh = (const float*)d_in[16 + off];
  const float* b_ih = (const float*)d_in[17 + off];
  const float* b_hh = (const float*)d_in[18 + off];
  const float* pW1  = (const float*)d_in[19 + off];
  const float* pb1  = (const float*)d_in[20 + off];
  const float* pW2  = (const float*)d_in[21 + off];
  const float* pb2  = (const float*)d_in[22 + off];
  const float* aW1  = (const float*)d_in[23 + off];
  const float* ab1  = (const float*)d_in[24 + off];
  const float* aW2  = (const float*)d_in[25 + off];
  const float* ab2  = (const float*)d_in[26 + off];
  const float* aW3  = (const float*)d_in[27 + off];
  const float* ab3  = (const float*)d_in[28 + off];

  repack_kernel<<<128, 256>>>(gatW, W_ih, W_hh, pW1, aW1, aW2);
  vkc_kernel<<<256, 256>>>(gesture_idx, demographics, emb_table,
                           dW1, db1, dW2, db2, jiW, jib,
                           gat_asrc, gat_adst, gat_b, ln_g, ln_b,
                           b_ih, b_hh,
                           pb1, pW2, pb2,
                           ab1, ab2,
                           aW3, ab3,
                           (float*)d_out);
}

// round 6
// speedup vs baseline: 1.5469x; 1.0321x over previous
#include <cuda_runtime.h>
#include <cstdint>

#define T_STEPS 64
typedef unsigned long long u64;

// ---------------- packed f32x2 helpers ----------------
__device__ __forceinline__ u64 ffma2(u64 a, u64 b, u64 c){
  u64 d; asm("fma.rn.f32x2 %0, %1, %2, %3;" : "=l"(d) : "l"(a), "l"(b), "l"(c)); return d;
}
__device__ __forceinline__ u64 addf2(u64 a, u64 b){
  u64 d; asm("add.rn.f32x2 %0, %1, %2;" : "=l"(d) : "l"(a), "l"(b)); return d;
}
__device__ __forceinline__ u64 pack2(float lo, float hi){
  u64 d; asm("mov.b64 %0, {%1, %2};" : "=l"(d) : "f"(lo), "f"(hi)); return d;
}
__device__ __forceinline__ float lo2(u64 a){ return __uint_as_float((unsigned)a); }
__device__ __forceinline__ float hi2(u64 a){ return __uint_as_float((unsigned)(a >> 32)); }
__device__ __forceinline__ float hsum2(u64 a){ return lo2(a) + hi2(a); }

#define BAR_ELEM(e) asm volatile("bar.sync %0, 64;" :: "r"((e)+1) : "memory")

// ---------------- repacked weights (loop-invariant, built by pre-kernel) ----------------
__device__ __align__(16) float gatP[49152];   // [l][k4][c][4] : gatW[l][4k4+i][c]
__device__ __align__(16) float WihP[65536];   // [k4][c][4]
__device__ __align__(16) float WhhP[65536];
__device__ __align__(16) float pW1P[8192];
__device__ __align__(16) float aW1P[8192];
__device__ __align__(16) float aW2P[2048];
__device__ __align__(16) float bsumP[512];    // b_ih + b_hh

__global__ void repack_kernel(const float* __restrict__ gatW, const float* __restrict__ W_ih,
                              const float* __restrict__ W_hh, const float* __restrict__ pW1,
                              const float* __restrict__ aW1,  const float* __restrict__ aW2,
                              const float* __restrict__ b_ih, const float* __restrict__ b_hh){
  for (int idx = blockIdx.x*blockDim.x + threadIdx.x; idx < 199168; idx += gridDim.x*blockDim.x){
    if (idx < 49152){
      int f = idx; int i = f&3, c = (f>>2)&127, k4 = (f>>9)&31, l = f>>14;
      gatP[f] = gatW[(l*128 + k4*4 + i)*128 + c];
    } else if (idx < 114688){
      int f = idx - 49152; int i = f&3, c = (f>>2)&511, k4 = f>>11;
      WihP[f] = W_ih[(k4*4+i)*512 + c];
    } else if (idx < 180224){
      int f = idx - 114688; int i = f&3, c = (f>>2)&511, k4 = f>>11;
      WhhP[f] = W_hh[(k4*4+i)*512 + c];
    } else if (idx < 188416){
      int f = idx - 180224; int i = f&3, c = (f>>2)&63, k4 = f>>8;
      pW1P[f] = pW1[(k4*4+i)*64 + c];
    } else if (idx < 196608){
      int f = idx - 188416; int i = f&3, c = (f>>2)&63, k4 = f>>8;
      aW1P[f] = aW1[(k4*4+i)*64 + c];
    } else if (idx < 198656){
      int f = idx - 196608; int i = f&3, c = (f>>2)&31, k4 = f>>7;
      aW2P[f] = aW2[(k4*4+i)*32 + c];
    } else {
      int f = idx - 198656;
      bsumP[f] = b_ih[f] + b_hh[f];
    }
  }
}

// ---------------- threefry2x32 (exact JAX, partitionable path) ----------------
__device__ __forceinline__ uint32_t rotl32(uint32_t x, int d){ return __funnelshift_l(x, x, d); }

__device__ __forceinline__ void threefry(uint32_t k0, uint32_t k1, uint32_t x0, uint32_t x1,
                                         uint32_t& o0, uint32_t& o1){
  uint32_t k2 = k0 ^ k1 ^ 0x1BD11BDAu;
  x0 += k0; x1 += k1;
  #define TFR(a,b,c,d) \
    x0 += x1; x1 = rotl32(x1,a); x1 ^= x0; \
    x0 += x1; x1 = rotl32(x1,b); x1 ^= x0; \
    x0 += x1; x1 = rotl32(x1,c); x1 ^= x0; \
    x0 += x1; x1 = rotl32(x1,d); x1 ^= x0;
  TFR(13,15,26,6)  x0 += k1; x1 += k2 + 1u;
  TFR(17,29,16,24) x0 += k2; x1 += k0 + 2u;
  TFR(13,15,26,6)  x0 += k0; x1 += k1 + 3u;
  TFR(17,29,16,24) x0 += k1; x1 += k2 + 4u;
  TFR(13,15,26,6)  x0 += k2; x1 += k0 + 5u;
  #undef TFR
  o0 = x0; o1 = x1;
}

// XLA ErfInv f32 (Giles polynomial)
__device__ __forceinline__ float erfinv_f(float x){
  float w = -__logf(fmaf(-x, x, 1.0f));
  float p;
  if (w < 5.0f){
    w -= 2.5f;
    p = 2.81022636e-08f;
    p = fmaf(p, w, 3.43273939e-07f);
    p = fmaf(p, w, -3.5233877e-06f);
    p = fmaf(p, w, -4.39150654e-06f);
    p = fmaf(p, w, 0.00021858087f);
    p = fmaf(p, w, -0.00125372503f);
    p = fmaf(p, w, -0.00417768164f);
    p = fmaf(p, w, 0.246640727f);
    p = fmaf(p, w, 1.50140941f);
  } else {
    w = sqrtf(w) - 3.0f;
    p = -0.000200214257f;
    p = fmaf(p, w, 0.000100950558f);
    p = fmaf(p, w, 0.00134934322f);
    p = fmaf(p, w, -0.00367342844f);
    p = fmaf(p, w, 0.00573950773f);
    p = fmaf(p, w, -0.0076224613f);
    p = fmaf(p, w, 0.00943887047f);
    p = fmaf(p, w, 1.00167406f);
    p = fmaf(p, w, 2.83297682f);
  }
  return p * x;
}

__device__ __forceinline__ float bits_to_normal(uint32_t bits){
  float f = __uint_as_float((bits >> 9) | 0x3f800000u) - 1.0f;
  const float lo = -0.99999994f;
  float u = fmaf(f, 2.0f, lo);
  u = fmaxf(u, lo);
  return 1.41421356237309515f * erfinv_f(u);
}

__device__ __forceinline__ float warpsum(float v){
  #pragma unroll
  for (int o = 16; o > 0; o >>= 1) v += __shfl_xor_sync(0xffffffffu, v, o);
  return v;
}
// packed (a,b) butterfly sum — two values, one 5-level chain
__device__ __forceinline__ u64 warpsum2(u64 v){
  #pragma unroll
  for (int o = 16; o > 0; o >>= 1){
    uint32_t l = (uint32_t)v, h = (uint32_t)(v >> 32);
    l = __shfl_xor_sync(0xffffffffu, l, o);
    h = __shfl_xor_sync(0xffffffffu, h, o);
    v = addf2(v, ((u64)h << 32) | l);
  }
  return v;
}
__device__ __forceinline__ float sig_(float x){ return __frcp_rn(1.0f + __expf(-x)); }
__device__ __forceinline__ float tanh_(float x){ return fmaf(2.0f, __frcp_rn(1.0f + __expf(-2.0f*x)), -1.0f); }

// ---------------- mega kernel: 1 block = 4 batch elems, 2 warps/elem, 2 CTA/SM ----------------
__global__ __launch_bounds__(256, 2)
void vkc_kernel(
  const int*   __restrict__ gesture_idx,
  const float* __restrict__ demographics,
  const float* __restrict__ emb_table,
  const float* __restrict__ dW1, const float* __restrict__ db1,
  const float* __restrict__ dW2, const float* __restrict__ db2,
  const float* __restrict__ jiW, const float* __restrict__ jib,
  const float* __restrict__ gat_asrc,
  const float* __restrict__ gat_adst, const float* __restrict__ gat_b,
  const float* __restrict__ ln_g, const float* __restrict__ ln_b,
  const float* __restrict__ pb1,
  const float* __restrict__ pW2, const float* __restrict__ pb2,
  const float* __restrict__ ab1,
  const float* __restrict__ ab2,
  const float* __restrict__ aW3, const float* __restrict__ ab3,
  float* __restrict__ out)
{
  __shared__ __align__(16) float xs[12][128];     // x state: 4 elems x 3 joints
  __shared__ __align__(16) float xp[12][128];     // GAT transformed
  __shared__ __align__(16) float hs[4][128];
  __shared__ __align__(16) float cs[4][128];
  __shared__ __align__(16) float gates[4][512];   // also comb[4][256] in setup
  __shared__ __align__(16) float scr[4][64];
  __shared__              float physs[4][3];

  const int tid  = threadIdx.x;
  const int w    = tid >> 5;     // warp 0..7
  const int lane = tid & 31;
  const int e    = w >> 1;       // local element 0..3
  const int wh   = w & 1;        // warp-half within element
  const int g    = blockIdx.x;   // 0..255
  const int b    = g*4 + e;
  const int wr   = e * 3;        // row base in xs/xp
  const int col  = tid & 127;
  const int rg   = tid >> 7;     // rowgroup 0/1 (setup GEMM only)
  const int c0   = wh*32 + lane; // 0..63: this thread's first GAT col

  // ---------------- setup: demo MLP + embedding -> combined ----------------
  {
    float dm[7];
    #pragma unroll
    for (int i = 0; i < 7; i++) dm[i] = demographics[b*7 + i];
    float a0 = db1[c0];
    #pragma unroll
    for (int i = 0; i < 7; i++) a0 = fmaf(dm[i], dW1[i*64 + c0], a0);
    scr[e][c0] = fmaxf(a0, 0.f);
  }
  __syncthreads();
  {
    const int gi = gesture_idx[b];
    #pragma unroll
    for (int q = 0; q < 2; q++){
      int c = wh*64 + 32*q + lane;
      gates[e][c] = emb_table[gi*128 + c];
      float acc = db2[c];
      #pragma unroll 4
      for (int k = 0; k < 64; k++) acc = fmaf(scr[e][k], dW2[k*128 + c], acc);
      gates[e][128 + c] = acc;
      hs[e][c] = 0.f; cs[e][c] = 0.f;
    }
  }
  __syncthreads();

  // ---------------- jf = relu(combined @ jiW + jib) -> xs ----------------
  {
    float acc[6];
    #pragma unroll
    for (int i = 0; i < 6; i++) acc[i] = 0.f;
    const int ebase = rg*2;
    #pragma unroll 4
    for (int k = 0; k < 256; k++){
      float w0 = jiW[0*32768 + k*128 + col];
      float w1 = jiW[1*32768 + k*128 + col];
      float w2 = jiW[2*32768 + k*128 + col];
      #pragma unroll
      for (int ee = 0; ee < 2; ee++){
        float cv = gates[ebase + ee][k];
        acc[ee*3+0] = fmaf(cv, w0, acc[ee*3+0]);
        acc[ee*3+1] = fmaf(cv, w1, acc[ee*3+1]);
        acc[ee*3+2] = fmaf(cv, w2, acc[ee*3+2]);
      }
    }
    #pragma unroll
    for (int ri = 0; ri < 6; ri++){
      int j = ri % 3;
      xs[rg*6 + ri][col] = fmaxf(acc[ri] + jib[j*128 + col], 0.f);
    }
  }
  __syncthreads();

  // ---------------- time loop ----------------
  for (int t = 0; t < T_STEPS; t++){
    // ===== 3 GAT layers (fully elem-local: 2 warps per element) =====
    #pragma unroll 1
    for (int l = 0; l < 3; l++){
      // elem-local GEMM: xp[wr+r][c0], xp[wr+r][c0+64] for r=0..2
      {
        const float* Wl = gatP + l*16384;
        u64 acc[6];
        #pragma unroll
        for (int i = 0; i < 6; i++) acc[i] = 0ull;
        #pragma unroll 4
        for (int k4 = 0; k4 < 32; k4++){
          const ulonglong2 wv0 = *reinterpret_cast<const ulonglong2*>(Wl + (k4*128 + c0     )*4);
          const ulonglong2 wv1 = *reinterpret_cast<const ulonglong2*>(Wl + (k4*128 + c0 + 64)*4);
          #pragma unroll
          for (int r = 0; r < 3; r++){
            const ulonglong2 xv = *reinterpret_cast<const ulonglong2*>(&xs[wr + r][k4*4]);
            acc[r*2+0] = ffma2(xv.x, wv0.x, acc[r*2+0]);
            acc[r*2+0] = ffma2(xv.y, wv0.y, acc[r*2+0]);
            acc[r*2+1] = ffma2(xv.x, wv1.x, acc[r*2+1]);
            acc[r*2+1] = ffma2(xv.y, wv1.y, acc[r*2+1]);
          }
        }
        #pragma unroll
        for (int r = 0; r < 3; r++){
          xp[wr + r][c0     ] = hsum2(acc[r*2+0]);
          xp[wr + r][c0 + 64] = hsum2(acc[r*2+1]);
        }
      }
      BAR_ELEM(e);

      // attention: 2 heads per warp
      {
        const float* as = gat_asrc + l*128;
        const float* ad = gat_adst + l*128;
        #pragma unroll
        for (int hh = 0; hh < 2; hh++){
          int h = 2*wh + hh;
          int c = h*32 + lane;
          float x0v = xp[wr+0][c], x1v = xp[wr+1][c], x2v = xp[wr+2][c];
          float av = as[c], dv = ad[c];
          float s0 = warpsum(x0v*av);
          float s1 = warpsum(x1v*av);
          float s2 = warpsum(x2v*av);
          float d1 = warpsum(x1v*dv);
          float d2 = warpsum(x2v*dv);
          float e10 = d1+s0; e10 = e10 > 0.f ? e10 : 0.2f*e10;
          float e11 = d1+s1; e11 = e11 > 0.f ? e11 : 0.2f*e11;
          float e21 = d2+s1; e21 = e21 > 0.f ? e21 : 0.2f*e21;
          float e22 = d2+s2; e22 = e22 > 0.f ? e22 : 0.2f*e22;
          float m1 = fmaxf(e10, e11);
          float p10 = __expf(e10-m1), p11 = __expf(e11-m1);
          float i1 = __frcp_rn(p10+p11);
          float m2 = fmaxf(e21, e22);
          float p21 = __expf(e21-m2), p22 = __expf(e22-m2);
          float i2 = __frcp_rn(p21+p22);
          xp[wr+1][c] = (p10*x0v + p11*x1v)*i1;
          xp[wr+2][c] = (p21*x1v + p22*x2v)*i2;
        }
      }
      BAR_ELEM(e);

      // bias + single-pass layernorm + relu + residual; wh0 -> rows 0,2 ; wh1 -> row 1
      {
        #pragma unroll
        for (int jj = 0; jj < 2; jj++){
          if (wh == 1 && jj == 1) break;
          int j = (wh == 0) ? (jj == 0 ? 0 : 2) : 1;
          float v[4];
          float s = 0.f, ss = 0.f;
          #pragma unroll
          for (int q = 0; q < 4; q++){
            int c = lane + 32*q;
            v[q] = xp[wr+j][c] + gat_b[l*128 + c];
            s += v[q];
            ss = fmaf(v[q], v[q], ss);
          }
          u64 red = warpsum2(pack2(s, ss));
          float mu  = lo2(red) * (1.f/128.f);
          float var = fmaf(-mu, mu, hi2(red) * (1.f/128.f));
          float inv = rsqrtf(var + 1e-5f);
          #pragma unroll
          for (int q = 0; q < 4; q++){
            int c = lane + 32*q;
            float y = (v[q]-mu)*inv*ln_g[l*128 + c] + ln_b[l*128 + c];
            xs[wr+j][c] = fmaxf(y, 0.f) + xs[wr+j][c];
          }
        }
      }
      BAR_ELEM(e);
    }

    __syncthreads();   // all elems' xs row2 + hs ready for block-wide LSTM GEMM

    // ===== LSTM gates GEMM (f32x2): gates[4][512] = w@W_ih + h@W_hh + (b_ih+b_hh) =====
    {
      const int c  = tid;
      const int c2 = tid + 256;
      const float bs1 = bsumP[c], bs2 = bsumP[c2];
      u64 accA[4], accB[4];
      #pragma unroll
      for (int ee = 0; ee < 4; ee++){ accA[ee] = pack2(bs1, 0.f); accB[ee] = pack2(bs2, 0.f); }
      #pragma unroll 2
      for (int k4 = 0; k4 < 32; k4++){
        const ulonglong2 wiA = *reinterpret_cast<const ulonglong2*>(WihP + (k4*512 + c )*4);
        const ulonglong2 wiB = *reinterpret_cast<const ulonglong2*>(WihP + (k4*512 + c2)*4);
        const ulonglong2 whA = *reinterpret_cast<const ulonglong2*>(WhhP + (k4*512 + c )*4);
        const ulonglong2 whB = *reinterpret_cast<const ulonglong2*>(WhhP + (k4*512 + c2)*4);
        #pragma unroll
        for (int ee = 0; ee < 4; ee++){
          const ulonglong2 xv = *reinterpret_cast<const ulonglong2*>(&xs[ee*3+2][k4*4]);
          const ulonglong2 hv = *reinterpret_cast<const ulonglong2*>(&hs[ee][k4*4]);
          u64 a = accA[ee], bb = accB[ee];
          a  = ffma2(xv.x, wiA.x, a );  a  = ffma2(xv.y, wiA.y, a );
          a  = ffma2(hv.x, whA.x, a );  a  = ffma2(hv.y, whA.y, a );
          bb = ffma2(xv.x, wiB.x, bb);  bb = ffma2(xv.y, wiB.y, bb);
          bb = ffma2(hv.x, whB.x, bb);  bb = ffma2(hv.y, whB.y, bb);
          accA[ee] = a; accB[ee] = bb;
        }
      }
      #pragma unroll
      for (int ee = 0; ee < 4; ee++){
        gates[ee][c]  = hsum2(accA[ee]);
        gates[ee][c2] = hsum2(accB[ee]);
      }
    }
    __syncthreads();

    // ===== LSTM pointwise (elem warps; bias already folded in) =====
    {
      #pragma unroll
      for (int qq = 0; qq < 2; qq++){
        int cx = lane + 32*(2*wh + qq);
        float gi = gates[e][cx];
        float gf = gates[e][128 + cx];
        float gg = gates[e][256 + cx];
        float go = gates[e][384 + cx];
        float cn = sig_(gf)*cs[e][cx] + sig_(gi)*tanh_(gg);
        float hn = sig_(go)*tanh_(cn);
        cs[e][cx] = cn; hs[e][cx] = hn;
      }
    }

    // ===== noise (elem-local): x += 0.05 * normal * (t/64); skip t=0 and t=63 =====
    if (t >= 1 && t < T_STEPS - 1){
      const float scale = 0.05f * (float)t * (1.0f/64.0f);
      uint32_t kt0, kt1;
      threefry(0u, 42u, 0u, (uint32_t)t, kt0, kt1);   // fold_in(key(42), t)
      #pragma unroll 1
      for (int ii = wh*32 + lane; ii < 384; ii += 64){
        uint32_t m = (uint32_t)(b*384 + ii);
        uint32_t o0, o1;
        threefry(kt0, kt1, 0u, m, o0, o1);
        xs[wr + (ii >> 7)][ii & 127] += scale * bits_to_normal(o0 ^ o1);
      }
    }
    BAR_ELEM(e);   // hs + noised xs complete within element

    // ===== output heads: wh0 = phys path, wh1 = act path =====
    float t2 = 0.f;
    if (wh == 0){
      u64 pa = 0ull, pb = 0ull;
      #pragma unroll 4
      for (int k4 = 0; k4 < 32; k4++){
        const ulonglong2 wA = *reinterpret_cast<const ulonglong2*>(pW1P + (k4*64 + lane   )*4);
        const ulonglong2 wB = *reinterpret_cast<const ulonglong2*>(pW1P + (k4*64 + lane+32)*4);
        const ulonglong2 hv = *reinterpret_cast<const ulonglong2*>(&hs[e][k4*4]);
        pa = ffma2(hv.x, wA.x, pa); pa = ffma2(hv.y, wA.y, pa);
        pb = ffma2(hv.x, wB.x, pb); pb = ffma2(hv.y, wB.y, pb);
      }
      float p_a = fmaxf(hsum2(pa) + pb1[lane],    0.f);
      float p_b = fmaxf(hsum2(pb) + pb1[lane+32], 0.f);
      float phys0 = warpsum(p_a*pW2[lane*3+0] + p_b*pW2[(lane+32)*3+0]) + pb2[0];
      float phys1 = warpsum(p_a*pW2[lane*3+1] + p_b*pW2[(lane+32)*3+1]) + pb2[1];
      float phys2 = warpsum(p_a*pW2[lane*3+2] + p_b*pW2[(lane+32)*3+2]) + pb2[2];
      if (lane == 0){ physs[e][0] = phys0; physs[e][1] = phys1; physs[e][2] = phys2; }
    } else {
      u64 aa = 0ull, ab = 0ull;
      #pragma unroll 4
      for (int k4 = 0; k4 < 32; k4++){
        const ulonglong2 wA = *reinterpret_cast<const ulonglong2*>(aW1P + (k4*64 + lane   )*4);
        const ulonglong2 wB = *reinterpret_cast<const ulonglong2*>(aW1P + (k4*64 + lane+32)*4);
        const ulonglong2 hv = *reinterpret_cast<const ulonglong2*>(&hs[e][k4*4]);
        aa = ffma2(hv.x, wA.x, aa); aa = ffma2(hv.y, wA.y, aa);
        ab = ffma2(hv.x, wB.x, ab); ab = ffma2(hv.y, wB.y, ab);
      }
      scr[e][lane]    = fmaxf(hsum2(aa) + ab1[lane],    0.f);
      scr[e][lane+32] = fmaxf(hsum2(ab) + ab1[lane+32], 0.f);
      __syncwarp();
      u64 t2a = 0ull;
      #pragma unroll
      for (int k4 = 0; k4 < 16; k4++){
        const ulonglong2 wv = *reinterpret_cast<const ulonglong2*>(aW2P + (k4*32 + lane)*4);
        const ulonglong2 sv = *reinterpret_cast<const ulonglong2*>(&scr[e][k4*4]);
        t2a = ffma2(sv.x, wv.x, t2a); t2a = ffma2(sv.y, wv.y, t2a);
      }
      t2 = fmaxf(hsum2(t2a) + ab2[lane], 0.f);
    }
    BAR_ELEM(e);

    if (wh == 1){
      float av0 = warpsum(t2*aW3[lane*3+0]) + ab3[0] + 0.1f*physs[e][0];
      float av1 = warpsum(t2*aW3[lane*3+1]) + ab3[1] + 0.1f*physs[e][1];
      float av2 = warpsum(t2*aW3[lane*3+2]) + ab3[2] + 0.1f*physs[e][2];
      if (lane < 3){
        float v = (lane == 0) ? av0 : ((lane == 1) ? av1 : av2);
        out[(b*T_STEPS + t)*3 + lane] = v;
      }
    }
    BAR_ELEM(e);   // out/scr/physs done; elem may run ahead into next step's GAT
  }
}

extern "C" void kernel_launch(void* const* d_in, const int* in_sizes, int n_in,
                              void* d_out, int out_size)
{
  const int off = (n_in >= 30) ? 1 : 0;  // 1 if sequence_length present at idx 2
  const int*   gesture_idx  = (const int*)  d_in[0];
  const float* demographics = (const float*)d_in[1];
  const float* emb_table = (const float*)d_in[2 + off];
  const float* dW1  = (const float*)d_in[3 + off];
  const float* db1  = (const float*)d_in[4 + off];
  const float* dW2  = (const float*)d_in[5 + off];
  const float* db2  = (const float*)d_in[6 + off];
  const float* jiW  = (const float*)d_in[7 + off];
  const float* jib  = (const float*)d_in[8 + off];
  const float* gatW = (const float*)d_in[9 + off];
  const float* gat_asrc = (const float*)d_in[10 + off];
  const float* gat_adst = (const float*)d_in[11 + off];
  const float* gat_b    = (const float*)d_in[12 + off];
  const float* ln_g = (const float*)d_in[13 + off];
  const float* ln_b = (const float*)d_in[14 + off];
  const float* W_ih = (const float*)d_in[15 + off];
  const float* W_hh = (const float*)d_in[16 + off];
  const float* b_ih = (const float*)d_in[17 + off];
  const float* b_hh = (const float*)d_in[18 + off];
  const float* pW1  = (const float*)d_in[19 + off];
  const float* pb1  = (const float*)d_in[20 + off];
  const float* pW2  = (const float*)d_in[21 + off];
  const float* pb2  = (const float*)d_in[22 + off];
  const float* aW1  = (const float*)d_in[23 + off];
  const float* ab1  = (const float*)d_in[24 + off];
  const float* aW2  = (const float*)d_in[25 + off];
  const float* ab2  = (const float*)d_in[26 + off];
  const float* aW3  = (const float*)d_in[27 + off];
  const float* ab3  = (const float*)d_in[28 + off];

  repack_kernel<<<128, 256>>>(gatW, W_ih, W_hh, pW1, aW1, aW2, b_ih, b_hh);
  vkc_kernel<<<256, 256>>>(gesture_idx, demographics, emb_table,
                           dW1, db1, dW2, db2, jiW, jib,
                           gat_asrc, gat_adst, gat_b, ln_g, ln_b,
                           pb1, pW2, pb2,
                           ab1, ab2,
                           aW3, ab3,
                           (float*)d_out);
}